// round 14
// baseline (speedup 1.0000x reference)
#include <cuda_runtime.h>
#include <cuda_bf16.h>
#include <math.h>
#include <stdint.h>

#define NB 2
#define NTOK 2048
#define DMODEL 1024
#define NH 16
#define DH 64
#define MROWS (NB*NTOK)          // 4096
#define MELEMS (MROWS*DMODEL)    // 4M

// ---- scratch (static device globals; no allocations) ----
__device__ float g_qbuf[MELEMS];              // q proj, float head-major [B*H, N, Dh]
__device__ float g_attn[MELEMS];              // flash out, row-major [B*N, D]
__device__ __nv_bfloat16 p_qh[MELEMS], p_ql[MELEMS];   // gated q planes, head-major
__device__ __nv_bfloat16 p_kh[MELEMS], p_kl[MELEMS];   // k planes, head-major
__device__ __nv_bfloat16 p_vh[MELEMS], p_vl[MELEMS];   // v planes, head-major

__device__ __forceinline__ float gelu_erf(float x){
    return 0.5f*x*(1.0f+erff(x*0.7071067811865476f));
}

__device__ __forceinline__ float ex2(float x){
    float r; asm("ex2.approx.ftz.f32 %0, %1;" : "=f"(r) : "f"(x)); return r;
}

// bf16 split: x = hi + lo (+ ~2^-16 residual). Pack pairs little-endian (x in low half).
__device__ __forceinline__ void split2(float x, float y, uint32_t& hi, uint32_t& lo){
    __nv_bfloat16 hx = __float2bfloat16(x), hy = __float2bfloat16(y);
    float rx = x - __bfloat162float(hx);
    float ry = y - __bfloat162float(hy);
    __nv_bfloat16 lx = __float2bfloat16(rx), ly = __float2bfloat16(ry);
    hi = ((uint32_t)__bfloat16_as_ushort(hy) << 16) | (uint32_t)__bfloat16_as_ushort(hx);
    lo = ((uint32_t)__bfloat16_as_ushort(ly) << 16) | (uint32_t)__bfloat16_as_ushort(lx);
}

__device__ __forceinline__ void mma_bf16(float* c, const uint32_t* a, uint32_t b0, uint32_t b1){
    asm volatile("mma.sync.aligned.m16n8k16.row.col.f32.bf16.bf16.f32 "
        "{%0,%1,%2,%3}, {%4,%5,%6,%7}, {%8,%9}, {%0,%1,%2,%3};"
        : "+f"(c[0]),"+f"(c[1]),"+f"(c[2]),"+f"(c[3])
        : "r"(a[0]),"r"(a[1]),"r"(a[2]),"r"(a[3]), "r"(b0),"r"(b1));
}

__device__ __forceinline__ void ldsm_x4_trans(uint32_t* r, const uint32_t* p){
    uint32_t addr = (uint32_t)__cvta_generic_to_shared(p);
    asm volatile("ldmatrix.sync.aligned.m8n8.x4.trans.shared.b16 {%0,%1,%2,%3}, [%4];"
        : "=r"(r[0]), "=r"(r[1]), "=r"(r[2]), "=r"(r[3]) : "r"(addr));
}

// ---------------- bf16x3 GEMM: C[M,N] = A[M,K] * W[N,K]^T (R10-exact) ----------------
// mode 0: row-major C [M, N].  mode 1: head-major float C [B*H, N_tok, Dh].
#define GST 20

__global__ __launch_bounds__(256) void gemm_bf16x3(
    const float* __restrict__ A, const float* __restrict__ Bw,
    float* __restrict__ C, int mode)
{
    __shared__ uint32_t Ah[128*GST], Al[128*GST], Bh[128*GST], Bl[128*GST];
    const int tid = threadIdx.x;
    const int wid = tid >> 5, lane = tid & 31;
    const int g = lane >> 2, tig = lane & 3;
    const int wm = (wid >> 2) * 64;
    const int wn = (wid & 3) * 32;
    const int m0 = blockIdx.y * 128;
    const int n0 = blockIdx.x * 128;

    float acc[4][4][4];
    #pragma unroll
    for (int mt=0;mt<4;mt++)
        #pragma unroll
        for (int nt=0;nt<4;nt++)
            #pragma unroll
            for (int i=0;i<4;i++) acc[mt][nt][i]=0.f;

    for (int k0 = 0; k0 < DMODEL; k0 += 32){
        #pragma unroll
        for (int t=0;t<4;t++){
            int li = tid + t*256;
            int row = li >> 3, c4 = (li & 7) * 4;
            int w = row*GST + (c4 >> 1);
            float4 av = *(const float4*)(A + (size_t)(m0+row)*DMODEL + k0 + c4);
            uint32_t h0,l0,h1,l1;
            split2(av.x, av.y, h0, l0); split2(av.z, av.w, h1, l1);
            Ah[w]=h0; Ah[w+1]=h1; Al[w]=l0; Al[w+1]=l1;
            float4 bv = *(const float4*)(Bw + (size_t)(n0+row)*DMODEL + k0 + c4);
            split2(bv.x, bv.y, h0, l0); split2(bv.z, bv.w, h1, l1);
            Bh[w]=h0; Bh[w+1]=h1; Bl[w]=l0; Bl[w+1]=l1;
        }
        __syncthreads();
        #pragma unroll
        for (int ks=0; ks<2; ks++){
            uint32_t afh[4][4], afl[4][4], bfh[4][2], bfl[4][2];
            #pragma unroll
            for (int mt=0;mt<4;mt++){
                int r = wm + mt*16;
                int w0 = (r+g)*GST + ks*8 + tig;
                int w1 = (r+g+8)*GST + ks*8 + tig;
                afh[mt][0]=Ah[w0]; afh[mt][1]=Ah[w1]; afh[mt][2]=Ah[w0+4]; afh[mt][3]=Ah[w1+4];
                afl[mt][0]=Al[w0]; afl[mt][1]=Al[w1]; afl[mt][2]=Al[w0+4]; afl[mt][3]=Al[w1+4];
            }
            #pragma unroll
            for (int nt=0;nt<4;nt++){
                int w = (wn+nt*8+g)*GST + ks*8 + tig;
                bfh[nt][0]=Bh[w]; bfh[nt][1]=Bh[w+4];
                bfl[nt][0]=Bl[w]; bfl[nt][1]=Bl[w+4];
            }
            #pragma unroll
            for (int mt=0;mt<4;mt++)
                #pragma unroll
                for (int nt=0;nt<4;nt++)
                    mma_bf16(acc[mt][nt], afh[mt], bfh[nt][0], bfh[nt][1]);
            #pragma unroll
            for (int mt=0;mt<4;mt++)
                #pragma unroll
                for (int nt=0;nt<4;nt++)
                    mma_bf16(acc[mt][nt], afh[mt], bfl[nt][0], bfl[nt][1]);
            #pragma unroll
            for (int mt=0;mt<4;mt++)
                #pragma unroll
                for (int nt=0;nt<4;nt++)
                    mma_bf16(acc[mt][nt], afl[mt], bfh[nt][0], bfh[nt][1]);
        }
        __syncthreads();
    }

    if (mode == 0){
        #pragma unroll
        for (int mt=0;mt<4;mt++){
            int m1 = m0 + wm + mt*16 + g;
            #pragma unroll
            for (int nt=0;nt<4;nt++){
                int n = n0 + wn + nt*8 + tig*2;
                *(float2*)(C + (size_t)m1*DMODEL + n)     = make_float2(acc[mt][nt][0], acc[mt][nt][1]);
                *(float2*)(C + (size_t)(m1+8)*DMODEL + n) = make_float2(acc[mt][nt][2], acc[mt][nt][3]);
            }
        }
    } else {
        #pragma unroll
        for (int mt=0;mt<4;mt++){
            int m1 = m0 + wm + mt*16 + g;
            int b_ = m1 >> 11;
            int r1 = m1 & (NTOK-1);
            #pragma unroll
            for (int nt=0;nt<4;nt++){
                int n = n0 + wn + nt*8 + tig*2;
                int h = n >> 6, d = n & 63;
                float* dst1 = C + (((size_t)(b_*NH+h)*NTOK + r1    )*DH + d);
                float* dst2 = C + (((size_t)(b_*NH+h)*NTOK + r1 + 8)*DH + d);
                *(float2*)dst1 = make_float2(acc[mt][nt][0], acc[mt][nt][1]);
                *(float2*)dst2 = make_float2(acc[mt][nt][2], acc[mt][nt][3]);
            }
        }
    }
}

// ---------------- gemm_kv: same mainloop, epilogue -> head-major bf16 hi/lo planes ----------------
__global__ __launch_bounds__(256) void gemm_kv(
    const float* __restrict__ A, const float* __restrict__ Bw,
    __nv_bfloat16* __restrict__ Ch, __nv_bfloat16* __restrict__ Cl)
{
    __shared__ uint32_t Ah[128*GST], Al[128*GST], Bh[128*GST], Bl[128*GST];
    const int tid = threadIdx.x;
    const int wid = tid >> 5, lane = tid & 31;
    const int g = lane >> 2, tig = lane & 3;
    const int wm = (wid >> 2) * 64;
    const int wn = (wid & 3) * 32;
    const int m0 = blockIdx.y * 128;
    const int n0 = blockIdx.x * 128;

    float acc[4][4][4];
    #pragma unroll
    for (int mt=0;mt<4;mt++)
        #pragma unroll
        for (int nt=0;nt<4;nt++)
            #pragma unroll
            for (int i=0;i<4;i++) acc[mt][nt][i]=0.f;

    for (int k0 = 0; k0 < DMODEL; k0 += 32){
        #pragma unroll
        for (int t=0;t<4;t++){
            int li = tid + t*256;
            int row = li >> 3, c4 = (li & 7) * 4;
            int w = row*GST + (c4 >> 1);
            float4 av = *(const float4*)(A + (size_t)(m0+row)*DMODEL + k0 + c4);
            uint32_t h0,l0,h1,l1;
            split2(av.x, av.y, h0, l0); split2(av.z, av.w, h1, l1);
            Ah[w]=h0; Ah[w+1]=h1; Al[w]=l0; Al[w+1]=l1;
            float4 bv = *(const float4*)(Bw + (size_t)(n0+row)*DMODEL + k0 + c4);
            split2(bv.x, bv.y, h0, l0); split2(bv.z, bv.w, h1, l1);
            Bh[w]=h0; Bh[w+1]=h1; Bl[w]=l0; Bl[w+1]=l1;
        }
        __syncthreads();
        #pragma unroll
        for (int ks=0; ks<2; ks++){
            uint32_t afh[4][4], afl[4][4], bfh[4][2], bfl[4][2];
            #pragma unroll
            for (int mt=0;mt<4;mt++){
                int r = wm + mt*16;
                int w0 = (r+g)*GST + ks*8 + tig;
                int w1 = (r+g+8)*GST + ks*8 + tig;
                afh[mt][0]=Ah[w0]; afh[mt][1]=Ah[w1]; afh[mt][2]=Ah[w0+4]; afh[mt][3]=Ah[w1+4];
                afl[mt][0]=Al[w0]; afl[mt][1]=Al[w1]; afl[mt][2]=Al[w0+4]; afl[mt][3]=Al[w1+4];
            }
            #pragma unroll
            for (int nt=0;nt<4;nt++){
                int w = (wn+nt*8+g)*GST + ks*8 + tig;
                bfh[nt][0]=Bh[w]; bfh[nt][1]=Bh[w+4];
                bfl[nt][0]=Bl[w]; bfl[nt][1]=Bl[w+4];
            }
            #pragma unroll
            for (int mt=0;mt<4;mt++)
                #pragma unroll
                for (int nt=0;nt<4;nt++)
                    mma_bf16(acc[mt][nt], afh[mt], bfh[nt][0], bfh[nt][1]);
            #pragma unroll
            for (int mt=0;mt<4;mt++)
                #pragma unroll
                for (int nt=0;nt<4;nt++)
                    mma_bf16(acc[mt][nt], afh[mt], bfl[nt][0], bfl[nt][1]);
            #pragma unroll
            for (int mt=0;mt<4;mt++)
                #pragma unroll
                for (int nt=0;nt<4;nt++)
                    mma_bf16(acc[mt][nt], afl[mt], bfh[nt][0], bfh[nt][1]);
        }
        __syncthreads();
    }

    // head-major bf16 hi/lo plane epilogue: plane word index = tok*32 + d/2
    uint32_t* Chw = (uint32_t*)Ch;
    uint32_t* Clw = (uint32_t*)Cl;
    #pragma unroll
    for (int mt=0;mt<4;mt++){
        int m1 = m0 + wm + mt*16 + g;
        int b_ = m1 >> 11;
        int r1 = m1 & (NTOK-1);
        #pragma unroll
        for (int nt=0;nt<4;nt++){
            int n = n0 + wn + nt*8 + tig*2;
            int h = n >> 6, d = n & 63;
            size_t w1 = ((size_t)(b_*NH+h)*NTOK + r1    )*32 + (d>>1);
            size_t w2 = ((size_t)(b_*NH+h)*NTOK + r1 + 8)*32 + (d>>1);
            uint32_t hw, lw;
            split2(acc[mt][nt][0], acc[mt][nt][1], hw, lw);
            Chw[w1] = hw; Clw[w1] = lw;
            split2(acc[mt][nt][2], acc[mt][nt][3], hw, lw);
            Chw[w2] = hw; Clw[w2] = lw;
        }
    }
}

// ---------------- QASS gate via tensor cores -> writes q hi/lo planes ----------------
#define KST 36
#define QSCALE 0.18033688011112042f   // 0.125 * log2(e)

__global__ __launch_bounds__(256) void qass_mma(
        const float* __restrict__ wg1, const float* __restrict__ wg2,
        const float* __restrict__ wb1, const float* __restrict__ wb2,
        const int* __restrict__ nctx)
{
    __shared__ uint32_t W1h[64*KST], W1l[64*KST], W2h[64*KST], W2l[64*KST];
    __shared__ float base_s[64];
    __shared__ float act[64];

    const int tid = threadIdx.x;
    const int wid = tid >> 5, lane = tid & 31;
    const int g = lane >> 2, tig = lane & 3;
    const int t0 = blockIdx.x * 128;
    const int h  = (t0 >> 11) & (NH-1);

    #pragma unroll
    for (int t=0;t<4;t++){
        int li = tid + t*256;
        int row = li >> 4, c4 = (li & 15)*4;
        int w = row*KST + (c4 >> 1);
        float4 v1 = *(const float4*)(wg1 + (size_t)row*64 + c4);
        uint32_t h0,l0,h1,l1;
        split2(v1.x,v1.y,h0,l0); split2(v1.z,v1.w,h1,l1);
        W1h[w]=h0; W1h[w+1]=h1; W1l[w]=l0; W1l[w+1]=l1;
        float4 v2 = *(const float4*)(wg2 + (size_t)row*64 + c4);
        split2(v2.x,v2.y,h0,l0); split2(v2.z,v2.w,h1,l1);
        W2h[w]=h0; W2h[w+1]=h1; W2l[w]=l0; W2l[w+1]=l1;
    }
    if (tid < 64){
        int iv = nctx[0];
        float n = (iv > 0 && iv < 100000000) ? (float)iv : __int_as_float(iv);
        act[tid] = gelu_erf(logf(n) * wb1[tid]);
    }
    __syncthreads();
    if (tid < 64){
        float s = 0.f;
        const float* w2row = wb2 + (size_t)(h*64 + tid)*64;
        #pragma unroll
        for (int k=0;k<64;k++) s = fmaf(act[k], w2row[k], s);
        base_s[tid] = s;
    }

    const float* Qw = g_qbuf + (size_t)(t0 + wid*16)*DH;
    uint32_t qh[4][4], ql[4][4];
    #pragma unroll
    for (int kc=0;kc<4;kc++){
        float2 a0 = *(const float2*)(Qw + (size_t)(g  )*DH + kc*16 + 2*tig);
        float2 a1 = *(const float2*)(Qw + (size_t)(g+8)*DH + kc*16 + 2*tig);
        float2 a2 = *(const float2*)(Qw + (size_t)(g  )*DH + kc*16 + 8 + 2*tig);
        float2 a3 = *(const float2*)(Qw + (size_t)(g+8)*DH + kc*16 + 8 + 2*tig);
        split2(a0.x,a0.y, qh[kc][0], ql[kc][0]);
        split2(a1.x,a1.y, qh[kc][1], ql[kc][1]);
        split2(a2.x,a2.y, qh[kc][2], ql[kc][2]);
        split2(a3.x,a3.y, qh[kc][3], ql[kc][3]);
    }
    __syncthreads();

    // S1 = Q @ wg1^T, bf16x3
    float sf[8][4];
    #pragma unroll
    for (int nt=0;nt<8;nt++)
        #pragma unroll
        for (int i=0;i<4;i++) sf[nt][i]=0.f;
    #pragma unroll
    for (int kc=0;kc<4;kc++){
        #pragma unroll
        for (int ng=0;ng<2;ng++){
            uint32_t kbh[4][2], kbl[4][2];
            #pragma unroll
            for (int j=0;j<4;j++){
                int kw = ((ng*4+j)*8+g)*KST + kc*8 + tig;
                kbh[j][0]=W1h[kw]; kbh[j][1]=W1h[kw+4];
                kbl[j][0]=W1l[kw]; kbl[j][1]=W1l[kw+4];
            }
            #pragma unroll
            for (int j=0;j<4;j++) mma_bf16(sf[ng*4+j], qh[kc], kbh[j][0], kbh[j][1]);
            #pragma unroll
            for (int j=0;j<4;j++) mma_bf16(sf[ng*4+j], qh[kc], kbl[j][0], kbl[j][1]);
            #pragma unroll
            for (int j=0;j<4;j++) mma_bf16(sf[ng*4+j], ql[kc], kbh[j][0], kbh[j][1]);
        }
    }

    // g1 = gelu(S1); repack into A-fragments (hi/lo)
    uint32_t ph[4][4], pl[4][4];
    #pragma unroll
    for (int nt=0;nt<8;nt++){
        float p00 = gelu_erf(sf[nt][0]);
        float p01 = gelu_erf(sf[nt][1]);
        float p10 = gelu_erf(sf[nt][2]);
        float p11 = gelu_erf(sf[nt][3]);
        uint32_t hi01, lo01, hi23, lo23;
        split2(p00, p01, hi01, lo01);
        split2(p10, p11, hi23, lo23);
        int kc = nt >> 1, half = (nt & 1) * 2;
        ph[kc][half  ] = hi01; pl[kc][half  ] = lo01;
        ph[kc][half+1] = hi23; pl[kc][half+1] = lo23;
    }

    // S2 = G1 @ wg2^T, bf16x3
    float s2[8][4];
    #pragma unroll
    for (int nt=0;nt<8;nt++)
        #pragma unroll
        for (int i=0;i<4;i++) s2[nt][i]=0.f;
    #pragma unroll
    for (int kc=0;kc<4;kc++){
        #pragma unroll
        for (int ng=0;ng<2;ng++){
            uint32_t kbh[4][2], kbl[4][2];
            #pragma unroll
            for (int j=0;j<4;j++){
                int kw = ((ng*4+j)*8+g)*KST + kc*8 + tig;
                kbh[j][0]=W2h[kw]; kbh[j][1]=W2h[kw+4];
                kbl[j][0]=W2l[kw]; kbl[j][1]=W2l[kw+4];
            }
            #pragma unroll
            for (int j=0;j<4;j++) mma_bf16(s2[ng*4+j], ph[kc], kbh[j][0], kbh[j][1]);
            #pragma unroll
            for (int j=0;j<4;j++) mma_bf16(s2[ng*4+j], ph[kc], kbl[j][0], kbl[j][1]);
            #pragma unroll
            for (int j=0;j<4;j++) mma_bf16(s2[ng*4+j], pl[kc], kbh[j][0], kbh[j][1]);
        }
    }

    // out = q * base * (1 + tanh(S2)) * QSCALE -> split into q planes
    const float* Qrow0 = g_qbuf + (size_t)(t0 + wid*16 + g    )*DH;
    const float* Qrow1 = g_qbuf + (size_t)(t0 + wid*16 + g + 8)*DH;
    uint32_t* Qhw = (uint32_t*)p_qh;
    uint32_t* Qlw = (uint32_t*)p_ql;
    size_t r0w = (size_t)(t0 + wid*16 + g    )*32;
    size_t r1w = (size_t)(t0 + wid*16 + g + 8)*32;
    #pragma unroll
    for (int nt=0;nt<8;nt++){
        int d0 = nt*8 + tig*2;
        int w = nt*4 + tig;
        float b0 = base_s[d0] * QSCALE, b1 = base_s[d0+1] * QSCALE;
        float2 q0 = *(const float2*)(Qrow0 + d0);
        float2 q1 = *(const float2*)(Qrow1 + d0);
        uint32_t hw, lw;
        split2(q0.x * b0 * (1.0f + tanhf(s2[nt][0])),
               q0.y * b1 * (1.0f + tanhf(s2[nt][1])), hw, lw);
        Qhw[r0w + w] = hw; Qlw[r0w + w] = lw;
        split2(q1.x * b0 * (1.0f + tanhf(s2[nt][2])),
               q1.y * b1 * (1.0f + tanhf(s2[nt][3])), hw, lw);
        Qhw[r1w + w] = hw; Qlw[r1w + w] = lw;
    }
}

// ---------------- bf16x3 flash attention: plane inputs, zero staging conversions ----------------
__global__ __launch_bounds__(256,2) void flash_bf16x3(float* __restrict__ outp)
{
    extern __shared__ uint32_t sm[];
    uint32_t* Ksh = sm;
    uint32_t* Ksl = Ksh + 64*KST;
    uint32_t* Vsh = Ksl + 64*KST;
    uint32_t* Vsl = Vsh + 64*KST;

    const int tid = threadIdx.x;
    const int wid = tid >> 5, lane = tid & 31;
    const int g = lane >> 2, tig = lane & 3;
    const int qt = blockIdx.x;
    const int bh = blockIdx.y;
    const int b_ = bh >> 4, h = bh & (NH-1);

    const uint32_t* Khg = (const uint32_t*)p_kh + (size_t)bh*NTOK*32;
    const uint32_t* Klg = (const uint32_t*)p_kl + (size_t)bh*NTOK*32;
    const uint32_t* Vhg = (const uint32_t*)p_vh + (size_t)bh*NTOK*32;
    const uint32_t* Vlg = (const uint32_t*)p_vl + (size_t)bh*NTOK*32;

    // Q fragments straight from planes (no conversion)
    uint32_t qh[4][4], ql[4][4];
    {
        const uint32_t* qhg = (const uint32_t*)p_qh + ((size_t)bh*NTOK + qt*128 + wid*16)*32;
        const uint32_t* qlg = (const uint32_t*)p_ql + ((size_t)bh*NTOK + qt*128 + wid*16)*32;
        #pragma unroll
        for (int kc=0;kc<4;kc++){
            int w0 = g*32 + kc*8 + tig;
            int w1 = (g+8)*32 + kc*8 + tig;
            qh[kc][0]=qhg[w0]; qh[kc][1]=qhg[w1]; qh[kc][2]=qhg[w0+4]; qh[kc][3]=qhg[w1+4];
            ql[kc][0]=qlg[w0]; ql[kc][1]=qlg[w1]; ql[kc][2]=qlg[w0+4]; ql[kc][3]=qlg[w1+4];
        }
    }

    float mrow[2] = {-1e30f, -1e30f};
    float lrow[2] = {0.f, 0.f};
    float of[8][4];
    #pragma unroll
    for (int nt=0;nt<8;nt++)
        #pragma unroll
        for (int i=0;i<4;i++) of[nt][i]=0.f;

    for (int kt = 0; kt < NTOK; kt += 64){
        __syncthreads();
        // stage K/V planes: pure LDG.128 -> STS.128
        #pragma unroll
        for (int t=0;t<8;t++){
            int li = tid + (t & 1)*256;         // 0..511
            const int plane = t >> 1;
            int row = li >> 3, chunk = li & 7;
            const uint32_t* src =
                (plane==0) ? Khg : (plane==1) ? Klg : (plane==2) ? Vhg : Vlg;
            uint32_t* dst =
                (plane==0) ? Ksh : (plane==1) ? Ksl : (plane==2) ? Vsh : Vsl;
            uint4 v = *(const uint4*)(src + (size_t)(kt+row)*32 + chunk*4);
            *(uint4*)(dst + row*KST + chunk*4) = v;
        }
        __syncthreads();

        // S = Q K^T, bf16x3, term-major groups of 4
        float sf[8][4];
        #pragma unroll
        for (int nt=0;nt<8;nt++)
            #pragma unroll
            for (int i=0;i<4;i++) sf[nt][i]=0.f;
        #pragma unroll
        for (int kc=0;kc<4;kc++){
            #pragma unroll
            for (int ng=0;ng<2;ng++){
                uint32_t kbh[4][2], kbl[4][2];
                #pragma unroll
                for (int j=0;j<4;j++){
                    int kw = ((ng*4+j)*8+g)*KST + kc*8 + tig;
                    kbh[j][0]=Ksh[kw]; kbh[j][1]=Ksh[kw+4];
                    kbl[j][0]=Ksl[kw]; kbl[j][1]=Ksl[kw+4];
                }
                #pragma unroll
                for (int j=0;j<4;j++)
                    mma_bf16(sf[ng*4+j], qh[kc], kbh[j][0], kbh[j][1]);
                #pragma unroll
                for (int j=0;j<4;j++)
                    mma_bf16(sf[ng*4+j], qh[kc], kbl[j][0], kbl[j][1]);
                #pragma unroll
                for (int j=0;j<4;j++)
                    mma_bf16(sf[ng*4+j], ql[kc], kbh[j][0], kbh[j][1]);
            }
        }

        // online softmax in log2 domain
        float mx0 = -1e30f, mx1 = -1e30f;
        #pragma unroll
        for (int nt=0;nt<8;nt++){
            mx0 = fmaxf(mx0, fmaxf(sf[nt][0], sf[nt][1]));
            mx1 = fmaxf(mx1, fmaxf(sf[nt][2], sf[nt][3]));
        }
        #pragma unroll
        for (int off=1; off<4; off<<=1){
            mx0 = fmaxf(mx0, __shfl_xor_sync(0xffffffffu, mx0, off));
            mx1 = fmaxf(mx1, __shfl_xor_sync(0xffffffffu, mx1, off));
        }
        float mn0 = fmaxf(mrow[0], mx0), mn1 = fmaxf(mrow[1], mx1);
        float c0 = ex2(mrow[0]-mn0), c1 = ex2(mrow[1]-mn1);
        mrow[0]=mn0; mrow[1]=mn1;

        uint32_t ph[4][4], pl[4][4];
        float rs0 = 0.f, rs1 = 0.f;
        #pragma unroll
        for (int nt=0;nt<8;nt++){
            float p00 = ex2(sf[nt][0]-mn0);
            float p01 = ex2(sf[nt][1]-mn0);
            float p10 = ex2(sf[nt][2]-mn1);
            float p11 = ex2(sf[nt][3]-mn1);
            rs0 += p00+p01; rs1 += p10+p11;
            uint32_t hi01, lo01, hi23, lo23;
            split2(p00, p01, hi01, lo01);
            split2(p10, p11, hi23, lo23);
            int kc = nt >> 1, half = (nt & 1) * 2;
            ph[kc][half  ] = hi01; pl[kc][half  ] = lo01;
            ph[kc][half+1] = hi23; pl[kc][half+1] = lo23;
            of[nt][0]*=c0; of[nt][1]*=c0; of[nt][2]*=c1; of[nt][3]*=c1;
        }
        lrow[0] = lrow[0]*c0 + rs0;
        lrow[1] = lrow[1]*c1 + rs1;

        // O += P @ V, bf16x3; term-major over ntp pairs
        #pragma unroll
        for (int kc=0;kc<4;kc++){
            int vrow = (kc*16 + (lane & 15))*KST + (lane >> 4)*4;
            #pragma unroll
            for (int np=0;np<2;np++){
                uint32_t vhA[4], vlA[4], vhB[4], vlB[4];
                ldsm_x4_trans(vhA, Vsh + vrow + (2*np  )*8);
                ldsm_x4_trans(vlA, Vsl + vrow + (2*np  )*8);
                ldsm_x4_trans(vhB, Vsh + vrow + (2*np+1)*8);
                ldsm_x4_trans(vlB, Vsl + vrow + (2*np+1)*8);
                mma_bf16(of[4*np+0], ph[kc], vhA[0], vhA[1]);
                mma_bf16(of[4*np+1], ph[kc], vhA[2], vhA[3]);
                mma_bf16(of[4*np+2], ph[kc], vhB[0], vhB[1]);
                mma_bf16(of[4*np+3], ph[kc], vhB[2], vhB[3]);
                mma_bf16(of[4*np+0], ph[kc], vlA[0], vlA[1]);
                mma_bf16(of[4*np+1], ph[kc], vlA[2], vlA[3]);
                mma_bf16(of[4*np+2], ph[kc], vlB[0], vlB[1]);
                mma_bf16(of[4*np+3], ph[kc], vlB[2], vlB[3]);
                mma_bf16(of[4*np+0], pl[kc], vhA[0], vhA[1]);
                mma_bf16(of[4*np+1], pl[kc], vhA[2], vhA[3]);
                mma_bf16(of[4*np+2], pl[kc], vhB[0], vhB[1]);
                mma_bf16(of[4*np+3], pl[kc], vhB[2], vhB[3]);
            }
        }
    }

    #pragma unroll
    for (int off=1; off<4; off<<=1){
        lrow[0] += __shfl_xor_sync(0xffffffffu, lrow[0], off);
        lrow[1] += __shfl_xor_sync(0xffffffffu, lrow[1], off);
    }
    float inv0 = 1.f/lrow[0], inv1 = 1.f/lrow[1];
    int row0 = qt*128 + wid*16 + g;
    #pragma unroll
    for (int nt=0;nt<8;nt++){
        int d0 = nt*8 + tig*2;
        *(float2*)(outp + (size_t)(b_*NTOK + row0    )*DMODEL + h*DH + d0) =
            make_float2(of[nt][0]*inv0, of[nt][1]*inv0);
        *(float2*)(outp + (size_t)(b_*NTOK + row0 + 8)*DMODEL + h*DH + d0) =
            make_float2(of[nt][2]*inv1, of[nt][3]*inv1);
    }
}

// ---------------- launch ----------------
extern "C" void kernel_launch(void* const* d_in, const int* in_sizes, int n_in,
                              void* d_out, int out_size)
{
    const float* query = (const float*)d_in[0];
    const float* key   = (const float*)d_in[1];
    const float* value = (const float*)d_in[2];
    // d_in[3] = allowed_mask: all-true in this problem; intentionally unused.
    const float* wq  = (const float*)d_in[4];
    const float* wk  = (const float*)d_in[5];
    const float* wv  = (const float*)d_in[6];
    const float* wo  = (const float*)d_in[7];
    const float* wb1 = (const float*)d_in[8];
    const float* wb2 = (const float*)d_in[9];
    const float* wg1 = (const float*)d_in[10];
    const float* wg2 = (const float*)d_in[11];
    const int*   nctx= (const int*)d_in[12];

    float *qb, *ab;
    __nv_bfloat16 *kh, *kl, *vh, *vl;
    cudaGetSymbolAddress((void**)&qb, g_qbuf);
    cudaGetSymbolAddress((void**)&ab, g_attn);
    cudaGetSymbolAddress((void**)&kh, p_kh);
    cudaGetSymbolAddress((void**)&kl, p_kl);
    cudaGetSymbolAddress((void**)&vh, p_vh);
    cudaGetSymbolAddress((void**)&vl, p_vl);

    const int FLASH_SMEM = 4*64*KST*4;   // 36864 B
    cudaFuncSetAttribute(flash_bf16x3,
                         cudaFuncAttributeMaxDynamicSharedMemorySize, FLASH_SMEM);

    dim3 ggrid(DMODEL/128, MROWS/128);   // (8, 32)
    gemm_bf16x3<<<ggrid, 256>>>(query, wq, qb, 1);
    gemm_kv<<<ggrid, 256>>>(key,   wk, kh, kl);
    gemm_kv<<<ggrid, 256>>>(value, wv, vh, vl);

    qass_mma<<<NB*NH*NTOK/128, 256>>>(wg1, wg2, wb1, wb2, nctx);

    flash_bf16x3<<<dim3(NTOK/128, NB*NH), 256, FLASH_SMEM>>>(ab);

    gemm_bf16x3<<<ggrid, 256>>>(ab, wo, (float*)d_out, 0);
}

// round 15
// speedup vs baseline: 1.1820x; 1.1820x over previous
#include <cuda_runtime.h>
#include <cuda_bf16.h>
#include <math.h>
#include <stdint.h>

#define NB 2
#define NTOK 2048
#define DMODEL 1024
#define NH 16
#define DH 64
#define MROWS (NB*NTOK)   // 4096

// ---- scratch (static device globals; no allocations) ----
__device__ float g_qbuf[NB*NH*NTOK*DH];   // head-major [B*H, N, Dh]
__device__ float g_kbuf[NB*NH*NTOK*DH];
__device__ float g_vbuf[NB*NH*NTOK*DH];
__device__ float g_attn[MROWS*DMODEL];    // row-major [B*N, D]

__device__ __forceinline__ float gelu_erf(float x){
    return 0.5f*x*(1.0f+erff(x*0.7071067811865476f));
}

__device__ __forceinline__ float ex2(float x){
    float r; asm("ex2.approx.ftz.f32 %0, %1;" : "=f"(r) : "f"(x)); return r;
}

// bf16 split: x = hi + lo (+ ~2^-16 residual). Pack pairs little-endian (x in low half).
__device__ __forceinline__ void split2(float x, float y, uint32_t& hi, uint32_t& lo){
    __nv_bfloat16 hx = __float2bfloat16(x), hy = __float2bfloat16(y);
    float rx = x - __bfloat162float(hx);
    float ry = y - __bfloat162float(hy);
    __nv_bfloat16 lx = __float2bfloat16(rx), ly = __float2bfloat16(ry);
    hi = ((uint32_t)__bfloat16_as_ushort(hy) << 16) | (uint32_t)__bfloat16_as_ushort(hx);
    lo = ((uint32_t)__bfloat16_as_ushort(ly) << 16) | (uint32_t)__bfloat16_as_ushort(lx);
}

__device__ __forceinline__ void mma_bf16(float* c, const uint32_t* a, uint32_t b0, uint32_t b1){
    asm volatile("mma.sync.aligned.m16n8k16.row.col.f32.bf16.bf16.f32 "
        "{%0,%1,%2,%3}, {%4,%5,%6,%7}, {%8,%9}, {%0,%1,%2,%3};"
        : "+f"(c[0]),"+f"(c[1]),"+f"(c[2]),"+f"(c[3])
        : "r"(a[0]),"r"(a[1]),"r"(a[2]),"r"(a[3]), "r"(b0),"r"(b1));
}

__device__ __forceinline__ void ldsm_x4_trans(uint32_t* r, const uint32_t* p){
    uint32_t addr = (uint32_t)__cvta_generic_to_shared(p);
    asm volatile("ldmatrix.sync.aligned.m8n8.x4.trans.shared.b16 {%0,%1,%2,%3}, [%4];"
        : "=r"(r[0]), "=r"(r[1]), "=r"(r[2]), "=r"(r[3]) : "r"(addr));
}

// ---------------- bf16x3 GEMM: C[M,N] = A[M,K] * W[N,K]^T, K=N=1024 ----------------
// R10-exact (125 regs -> 2 CTAs/SM; do NOT fatten the signature).
// mode 0: row-major C [M, N].  mode 1: head-major C [B*H, N_tok, Dh].
#define GST 20

__global__ __launch_bounds__(256) void gemm_bf16x3(
    const float* __restrict__ A, const float* __restrict__ Bw,
    float* __restrict__ C, int mode)
{
    __shared__ uint32_t Ah[128*GST], Al[128*GST], Bh[128*GST], Bl[128*GST];
    const int tid = threadIdx.x;
    const int wid = tid >> 5, lane = tid & 31;
    const int g = lane >> 2, tig = lane & 3;
    const int wm = (wid >> 2) * 64;
    const int wn = (wid & 3) * 32;
    const int m0 = blockIdx.y * 128;
    const int n0 = blockIdx.x * 128;

    float acc[4][4][4];
    #pragma unroll
    for (int mt=0;mt<4;mt++)
        #pragma unroll
        for (int nt=0;nt<4;nt++)
            #pragma unroll
            for (int i=0;i<4;i++) acc[mt][nt][i]=0.f;

    for (int k0 = 0; k0 < DMODEL; k0 += 32){
        #pragma unroll
        for (int t=0;t<4;t++){
            int li = tid + t*256;
            int row = li >> 3, c4 = (li & 7) * 4;
            int w = row*GST + (c4 >> 1);
            float4 av = *(const float4*)(A + (size_t)(m0+row)*DMODEL + k0 + c4);
            uint32_t h0,l0,h1,l1;
            split2(av.x, av.y, h0, l0); split2(av.z, av.w, h1, l1);
            Ah[w]=h0; Ah[w+1]=h1; Al[w]=l0; Al[w+1]=l1;
            float4 bv = *(const float4*)(Bw + (size_t)(n0+row)*DMODEL + k0 + c4);
            split2(bv.x, bv.y, h0, l0); split2(bv.z, bv.w, h1, l1);
            Bh[w]=h0; Bh[w+1]=h1; Bl[w]=l0; Bl[w+1]=l1;
        }
        __syncthreads();
        #pragma unroll
        for (int ks=0; ks<2; ks++){
            uint32_t afh[4][4], afl[4][4], bfh[4][2], bfl[4][2];
            #pragma unroll
            for (int mt=0;mt<4;mt++){
                int r = wm + mt*16;
                int w0 = (r+g)*GST + ks*8 + tig;
                int w1 = (r+g+8)*GST + ks*8 + tig;
                afh[mt][0]=Ah[w0]; afh[mt][1]=Ah[w1]; afh[mt][2]=Ah[w0+4]; afh[mt][3]=Ah[w1+4];
                afl[mt][0]=Al[w0]; afl[mt][1]=Al[w1]; afl[mt][2]=Al[w0+4]; afl[mt][3]=Al[w1+4];
            }
            #pragma unroll
            for (int nt=0;nt<4;nt++){
                int w = (wn+nt*8+g)*GST + ks*8 + tig;
                bfh[nt][0]=Bh[w]; bfh[nt][1]=Bh[w+4];
                bfl[nt][0]=Bl[w]; bfl[nt][1]=Bl[w+4];
            }
            #pragma unroll
            for (int mt=0;mt<4;mt++)
                #pragma unroll
                for (int nt=0;nt<4;nt++)
                    mma_bf16(acc[mt][nt], afh[mt], bfh[nt][0], bfh[nt][1]);
            #pragma unroll
            for (int mt=0;mt<4;mt++)
                #pragma unroll
                for (int nt=0;nt<4;nt++)
                    mma_bf16(acc[mt][nt], afh[mt], bfl[nt][0], bfl[nt][1]);
            #pragma unroll
            for (int mt=0;mt<4;mt++)
                #pragma unroll
                for (int nt=0;nt<4;nt++)
                    mma_bf16(acc[mt][nt], afl[mt], bfh[nt][0], bfh[nt][1]);
        }
        __syncthreads();
    }

    if (mode == 0){
        #pragma unroll
        for (int mt=0;mt<4;mt++){
            int m1 = m0 + wm + mt*16 + g;
            #pragma unroll
            for (int nt=0;nt<4;nt++){
                int n = n0 + wn + nt*8 + tig*2;
                *(float2*)(C + (size_t)m1*DMODEL + n)     = make_float2(acc[mt][nt][0], acc[mt][nt][1]);
                *(float2*)(C + (size_t)(m1+8)*DMODEL + n) = make_float2(acc[mt][nt][2], acc[mt][nt][3]);
            }
        }
    } else {
        #pragma unroll
        for (int mt=0;mt<4;mt++){
            int m1 = m0 + wm + mt*16 + g;
            int b_ = m1 >> 11;
            int r1 = m1 & (NTOK-1);
            #pragma unroll
            for (int nt=0;nt<4;nt++){
                int n = n0 + wn + nt*8 + tig*2;
                int h = n >> 6, d = n & 63;
                float* dst1 = C + (((size_t)(b_*NH+h)*NTOK + r1    )*DH + d);
                float* dst2 = C + (((size_t)(b_*NH+h)*NTOK + r1 + 8)*DH + d);
                *(float2*)dst1 = make_float2(acc[mt][nt][0], acc[mt][nt][1]);
                *(float2*)dst2 = make_float2(acc[mt][nt][2], acc[mt][nt][3]);
            }
        }
    }
}

// ---------------- QASS gate via tensor cores (R13-exact) ----------------
#define KST 36
#define QSCALE 0.18033688011112042f   // 0.125 * log2(e)

__global__ __launch_bounds__(256) void qass_mma(
        const float* __restrict__ wg1, const float* __restrict__ wg2,
        const float* __restrict__ wb1, const float* __restrict__ wb2,
        const int* __restrict__ nctx)
{
    __shared__ uint32_t W1h[64*KST], W1l[64*KST], W2h[64*KST], W2l[64*KST];
    __shared__ float base_s[64];
    __shared__ float act[64];

    const int tid = threadIdx.x;
    const int wid = tid >> 5, lane = tid & 31;
    const int g = lane >> 2, tig = lane & 3;
    const int t0 = blockIdx.x * 128;
    const int h  = (t0 >> 11) & (NH-1);

    #pragma unroll
    for (int t=0;t<4;t++){
        int li = tid + t*256;
        int row = li >> 4, c4 = (li & 15)*4;
        int w = row*KST + (c4 >> 1);
        float4 v1 = *(const float4*)(wg1 + (size_t)row*64 + c4);
        uint32_t h0,l0,h1,l1;
        split2(v1.x,v1.y,h0,l0); split2(v1.z,v1.w,h1,l1);
        W1h[w]=h0; W1h[w+1]=h1; W1l[w]=l0; W1l[w+1]=l1;
        float4 v2 = *(const float4*)(wg2 + (size_t)row*64 + c4);
        split2(v2.x,v2.y,h0,l0); split2(v2.z,v2.w,h1,l1);
        W2h[w]=h0; W2h[w+1]=h1; W2l[w]=l0; W2l[w+1]=l1;
    }
    if (tid < 64){
        int iv = nctx[0];
        float n = (iv > 0 && iv < 100000000) ? (float)iv : __int_as_float(iv);
        act[tid] = gelu_erf(logf(n) * wb1[tid]);
    }
    __syncthreads();
    if (tid < 64){
        float s = 0.f;
        const float* w2row = wb2 + (size_t)(h*64 + tid)*64;
        #pragma unroll
        for (int k=0;k<64;k++) s = fmaf(act[k], w2row[k], s);
        base_s[tid] = s;
    }

    const float* Qw = g_qbuf + (size_t)(t0 + wid*16)*DH;
    uint32_t qh[4][4], ql[4][4];
    #pragma unroll
    for (int kc=0;kc<4;kc++){
        float2 a0 = *(const float2*)(Qw + (size_t)(g  )*DH + kc*16 + 2*tig);
        float2 a1 = *(const float2*)(Qw + (size_t)(g+8)*DH + kc*16 + 2*tig);
        float2 a2 = *(const float2*)(Qw + (size_t)(g  )*DH + kc*16 + 8 + 2*tig);
        float2 a3 = *(const float2*)(Qw + (size_t)(g+8)*DH + kc*16 + 8 + 2*tig);
        split2(a0.x,a0.y, qh[kc][0], ql[kc][0]);
        split2(a1.x,a1.y, qh[kc][1], ql[kc][1]);
        split2(a2.x,a2.y, qh[kc][2], ql[kc][2]);
        split2(a3.x,a3.y, qh[kc][3], ql[kc][3]);
    }
    __syncthreads();

    float sf[8][4];
    #pragma unroll
    for (int nt=0;nt<8;nt++)
        #pragma unroll
        for (int i=0;i<4;i++) sf[nt][i]=0.f;
    #pragma unroll
    for (int kc=0;kc<4;kc++){
        #pragma unroll
        for (int ng=0;ng<2;ng++){
            uint32_t kbh[4][2], kbl[4][2];
            #pragma unroll
            for (int j=0;j<4;j++){
                int kw = ((ng*4+j)*8+g)*KST + kc*8 + tig;
                kbh[j][0]=W1h[kw]; kbh[j][1]=W1h[kw+4];
                kbl[j][0]=W1l[kw]; kbl[j][1]=W1l[kw+4];
            }
            #pragma unroll
            for (int j=0;j<4;j++) mma_bf16(sf[ng*4+j], qh[kc], kbh[j][0], kbh[j][1]);
            #pragma unroll
            for (int j=0;j<4;j++) mma_bf16(sf[ng*4+j], qh[kc], kbl[j][0], kbl[j][1]);
            #pragma unroll
            for (int j=0;j<4;j++) mma_bf16(sf[ng*4+j], ql[kc], kbh[j][0], kbh[j][1]);
        }
    }

    uint32_t ph[4][4], pl[4][4];
    #pragma unroll
    for (int nt=0;nt<8;nt++){
        float p00 = gelu_erf(sf[nt][0]);
        float p01 = gelu_erf(sf[nt][1]);
        float p10 = gelu_erf(sf[nt][2]);
        float p11 = gelu_erf(sf[nt][3]);
        uint32_t hi01, lo01, hi23, lo23;
        split2(p00, p01, hi01, lo01);
        split2(p10, p11, hi23, lo23);
        int kc = nt >> 1, half = (nt & 1) * 2;
        ph[kc][half  ] = hi01; pl[kc][half  ] = lo01;
        ph[kc][half+1] = hi23; pl[kc][half+1] = lo23;
    }

    float s2[8][4];
    #pragma unroll
    for (int nt=0;nt<8;nt++)
        #pragma unroll
        for (int i=0;i<4;i++) s2[nt][i]=0.f;
    #pragma unroll
    for (int kc=0;kc<4;kc++){
        #pragma unroll
        for (int ng=0;ng<2;ng++){
            uint32_t kbh[4][2], kbl[4][2];
            #pragma unroll
            for (int j=0;j<4;j++){
                int kw = ((ng*4+j)*8+g)*KST + kc*8 + tig;
                kbh[j][0]=W2h[kw]; kbh[j][1]=W2h[kw+4];
                kbl[j][0]=W2l[kw]; kbl[j][1]=W2l[kw+4];
            }
            #pragma unroll
            for (int j=0;j<4;j++) mma_bf16(s2[ng*4+j], ph[kc], kbh[j][0], kbh[j][1]);
            #pragma unroll
            for (int j=0;j<4;j++) mma_bf16(s2[ng*4+j], ph[kc], kbl[j][0], kbl[j][1]);
            #pragma unroll
            for (int j=0;j<4;j++) mma_bf16(s2[ng*4+j], pl[kc], kbh[j][0], kbh[j][1]);
        }
    }

    float* Qrow0 = g_qbuf + (size_t)(t0 + wid*16 + g    )*DH;
    float* Qrow1 = g_qbuf + (size_t)(t0 + wid*16 + g + 8)*DH;
    #pragma unroll
    for (int nt=0;nt<8;nt++){
        int d0 = nt*8 + tig*2;
        float b0 = base_s[d0] * QSCALE, b1 = base_s[d0+1] * QSCALE;
        float2 q0 = *(float2*)(Qrow0 + d0);
        float2 q1 = *(float2*)(Qrow1 + d0);
        *(float2*)(Qrow0 + d0) = make_float2(
            q0.x * b0 * (1.0f + tanhf(s2[nt][0])),
            q0.y * b1 * (1.0f + tanhf(s2[nt][1])));
        *(float2*)(Qrow1 + d0) = make_float2(
            q1.x * b0 * (1.0f + tanhf(s2[nt][2])),
            q1.y * b1 * (1.0f + tanhf(s2[nt][3])));
    }
}

// ---------------- bf16x3 flash attention (R13-exact) ----------------
__global__ __launch_bounds__(256,2) void flash_bf16x3(float* __restrict__ outp)
{
    extern __shared__ uint32_t sm[];
    uint32_t* Ksh = sm;
    uint32_t* Ksl = Ksh + 64*KST;
    uint32_t* Vsh = Ksl + 64*KST;
    uint32_t* Vsl = Vsh + 64*KST;

    const int tid = threadIdx.x;
    const int wid = tid >> 5, lane = tid & 31;
    const int g = lane >> 2, tig = lane & 3;
    const int qt = blockIdx.x;
    const int bh = blockIdx.y;
    const int b_ = bh >> 4, h = bh & (NH-1);
    const float* Qg = g_qbuf + ((size_t)bh*NTOK + qt*128)*DH;
    const float* Kg = g_kbuf + (size_t)bh*NTOK*DH;
    const float* Vg = g_vbuf + (size_t)bh*NTOK*DH;

    uint32_t qh[4][4], ql[4][4];
    {
        const float* Qw = Qg + (size_t)(wid*16)*DH;
        #pragma unroll
        for (int kc=0;kc<4;kc++){
            float2 a0 = *(const float2*)(Qw + (size_t)(g  )*DH + kc*16 + 2*tig);
            float2 a1 = *(const float2*)(Qw + (size_t)(g+8)*DH + kc*16 + 2*tig);
            float2 a2 = *(const float2*)(Qw + (size_t)(g  )*DH + kc*16 + 8 + 2*tig);
            float2 a3 = *(const float2*)(Qw + (size_t)(g+8)*DH + kc*16 + 8 + 2*tig);
            split2(a0.x,a0.y, qh[kc][0], ql[kc][0]);
            split2(a1.x,a1.y, qh[kc][1], ql[kc][1]);
            split2(a2.x,a2.y, qh[kc][2], ql[kc][2]);
            split2(a3.x,a3.y, qh[kc][3], ql[kc][3]);
        }
    }

    float mrow[2] = {-1e30f, -1e30f};
    float lrow[2] = {0.f, 0.f};
    float of[8][4];
    #pragma unroll
    for (int nt=0;nt<8;nt++)
        #pragma unroll
        for (int i=0;i<4;i++) of[nt][i]=0.f;

    for (int kt = 0; kt < NTOK; kt += 64){
        __syncthreads();
        #pragma unroll
        for (int t=0;t<4;t++){
            int li = tid + t*256;
            int row = li >> 4, c4 = (li & 15)*4;
            int w = row*KST + (c4 >> 1);
            float4 kv = *(const float4*)(Kg + (size_t)(kt+row)*DH + c4);
            uint32_t h0,l0,h1,l1;
            split2(kv.x,kv.y,h0,l0); split2(kv.z,kv.w,h1,l1);
            Ksh[w]=h0; Ksh[w+1]=h1; Ksl[w]=l0; Ksl[w+1]=l1;
            float4 vv = *(const float4*)(Vg + (size_t)(kt+row)*DH + c4);
            split2(vv.x,vv.y,h0,l0); split2(vv.z,vv.w,h1,l1);
            Vsh[w]=h0; Vsh[w+1]=h1; Vsl[w]=l0; Vsl[w+1]=l1;
        }
        __syncthreads();

        float sf[8][4];
        #pragma unroll
        for (int nt=0;nt<8;nt++)
            #pragma unroll
            for (int i=0;i<4;i++) sf[nt][i]=0.f;
        #pragma unroll
        for (int kc=0;kc<4;kc++){
            #pragma unroll
            for (int ng=0;ng<2;ng++){
                uint32_t kbh[4][2], kbl[4][2];
                #pragma unroll
                for (int j=0;j<4;j++){
                    int kw = ((ng*4+j)*8+g)*KST + kc*8 + tig;
                    kbh[j][0]=Ksh[kw]; kbh[j][1]=Ksh[kw+4];
                    kbl[j][0]=Ksl[kw]; kbl[j][1]=Ksl[kw+4];
                }
                #pragma unroll
                for (int j=0;j<4;j++)
                    mma_bf16(sf[ng*4+j], qh[kc], kbh[j][0], kbh[j][1]);
                #pragma unroll
                for (int j=0;j<4;j++)
                    mma_bf16(sf[ng*4+j], qh[kc], kbl[j][0], kbl[j][1]);
                #pragma unroll
                for (int j=0;j<4;j++)
                    mma_bf16(sf[ng*4+j], ql[kc], kbh[j][0], kbh[j][1]);
            }
        }

        float mx0 = -1e30f, mx1 = -1e30f;
        #pragma unroll
        for (int nt=0;nt<8;nt++){
            mx0 = fmaxf(mx0, fmaxf(sf[nt][0], sf[nt][1]));
            mx1 = fmaxf(mx1, fmaxf(sf[nt][2], sf[nt][3]));
        }
        #pragma unroll
        for (int off=1; off<4; off<<=1){
            mx0 = fmaxf(mx0, __shfl_xor_sync(0xffffffffu, mx0, off));
            mx1 = fmaxf(mx1, __shfl_xor_sync(0xffffffffu, mx1, off));
        }
        float mn0 = fmaxf(mrow[0], mx0), mn1 = fmaxf(mrow[1], mx1);
        float c0 = ex2(mrow[0]-mn0), c1 = ex2(mrow[1]-mn1);
        mrow[0]=mn0; mrow[1]=mn1;

        uint32_t ph[4][4], pl[4][4];
        float rs0 = 0.f, rs1 = 0.f;
        #pragma unroll
        for (int nt=0;nt<8;nt++){
            float p00 = ex2(sf[nt][0]-mn0);
            float p01 = ex2(sf[nt][1]-mn0);
            float p10 = ex2(sf[nt][2]-mn1);
            float p11 = ex2(sf[nt][3]-mn1);
            rs0 += p00+p01; rs1 += p10+p11;
            uint32_t hi01, lo01, hi23, lo23;
            split2(p00, p01, hi01, lo01);
            split2(p10, p11, hi23, lo23);
            int kc = nt >> 1, half = (nt & 1) * 2;
            ph[kc][half  ] = hi01; pl[kc][half  ] = lo01;
            ph[kc][half+1] = hi23; pl[kc][half+1] = lo23;
            of[nt][0]*=c0; of[nt][1]*=c0; of[nt][2]*=c1; of[nt][3]*=c1;
        }
        lrow[0] = lrow[0]*c0 + rs0;
        lrow[1] = lrow[1]*c1 + rs1;

        #pragma unroll
        for (int kc=0;kc<4;kc++){
            int vrow = (kc*16 + (lane & 15))*KST + (lane >> 4)*4;
            #pragma unroll
            for (int np=0;np<2;np++){
                uint32_t vhA[4], vlA[4], vhB[4], vlB[4];
                ldsm_x4_trans(vhA, Vsh + vrow + (2*np  )*8);
                ldsm_x4_trans(vlA, Vsl + vrow + (2*np  )*8);
                ldsm_x4_trans(vhB, Vsh + vrow + (2*np+1)*8);
                ldsm_x4_trans(vlB, Vsl + vrow + (2*np+1)*8);
                mma_bf16(of[4*np+0], ph[kc], vhA[0], vhA[1]);
                mma_bf16(of[4*np+1], ph[kc], vhA[2], vhA[3]);
                mma_bf16(of[4*np+2], ph[kc], vhB[0], vhB[1]);
                mma_bf16(of[4*np+3], ph[kc], vhB[2], vhB[3]);
                mma_bf16(of[4*np+0], ph[kc], vlA[0], vlA[1]);
                mma_bf16(of[4*np+1], ph[kc], vlA[2], vlA[3]);
                mma_bf16(of[4*np+2], ph[kc], vlB[0], vlB[1]);
                mma_bf16(of[4*np+3], ph[kc], vlB[2], vlB[3]);
                mma_bf16(of[4*np+0], pl[kc], vhA[0], vhA[1]);
                mma_bf16(of[4*np+1], pl[kc], vhA[2], vhA[3]);
                mma_bf16(of[4*np+2], pl[kc], vhB[0], vhB[1]);
                mma_bf16(of[4*np+3], pl[kc], vhB[2], vhB[3]);
            }
        }
    }

    #pragma unroll
    for (int off=1; off<4; off<<=1){
        lrow[0] += __shfl_xor_sync(0xffffffffu, lrow[0], off);
        lrow[1] += __shfl_xor_sync(0xffffffffu, lrow[1], off);
    }
    float inv0 = 1.f/lrow[0], inv1 = 1.f/lrow[1];
    int row0 = qt*128 + wid*16 + g;
    #pragma unroll
    for (int nt=0;nt<8;nt++){
        int d0 = nt*8 + tig*2;
        *(float2*)(outp + (size_t)(b_*NTOK + row0    )*DMODEL + h*DH + d0) =
            make_float2(of[nt][0]*inv0, of[nt][1]*inv0);
        *(float2*)(outp + (size_t)(b_*NTOK + row0 + 8)*DMODEL + h*DH + d0) =
            make_float2(of[nt][2]*inv1, of[nt][3]*inv1);
    }
}

// ---------------- launch: fork independent GEMMs across streams ----------------
extern "C" void kernel_launch(void* const* d_in, const int* in_sizes, int n_in,
                              void* d_out, int out_size)
{
    const float* query = (const float*)d_in[0];
    const float* key   = (const float*)d_in[1];
    const float* value = (const float*)d_in[2];
    // d_in[3] = allowed_mask: all-true in this problem; intentionally unused.
    const float* wq  = (const float*)d_in[4];
    const float* wk  = (const float*)d_in[5];
    const float* wv  = (const float*)d_in[6];
    const float* wo  = (const float*)d_in[7];
    const float* wb1 = (const float*)d_in[8];
    const float* wb2 = (const float*)d_in[9];
    const float* wg1 = (const float*)d_in[10];
    const float* wg2 = (const float*)d_in[11];
    const int*   nctx= (const int*)d_in[12];

    float *qb, *kb, *vb, *ab;
    cudaGetSymbolAddress((void**)&qb, g_qbuf);
    cudaGetSymbolAddress((void**)&kb, g_kbuf);
    cudaGetSymbolAddress((void**)&vb, g_vbuf);
    cudaGetSymbolAddress((void**)&ab, g_attn);

    const int FLASH_SMEM = 4*64*KST*4;   // 36864 B
    cudaFuncSetAttribute(flash_bf16x3,
                         cudaFuncAttributeMaxDynamicSharedMemorySize, FLASH_SMEM);

    // Streams/events created once on the (uncaptured) correctness call; the
    // captured call only records/waits, forming a fork-join graph. No device
    // memory is allocated. Work is identical on every call.
    static cudaStream_t s1 = nullptr, s2 = nullptr;
    static cudaEvent_t e0, e1, e2;
    if (s1 == nullptr){
        cudaStreamCreateWithFlags(&s1, cudaStreamNonBlocking);
        cudaStreamCreateWithFlags(&s2, cudaStreamNonBlocking);
        cudaEventCreateWithFlags(&e0, cudaEventDisableTiming);
        cudaEventCreateWithFlags(&e1, cudaEventDisableTiming);
        cudaEventCreateWithFlags(&e2, cudaEventDisableTiming);
    }

    dim3 ggrid(DMODEL/128, MROWS/128);   // (8, 32)

    // fork: k/v projections on side streams, q+qass on main stream
    cudaEventRecord(e0, 0);
    cudaStreamWaitEvent(s1, e0, 0);
    cudaStreamWaitEvent(s2, e0, 0);

    gemm_bf16x3<<<ggrid, 256, 0, s1>>>(key,   wk, kb, 1);
    gemm_bf16x3<<<ggrid, 256, 0, s2>>>(value, wv, vb, 1);
    gemm_bf16x3<<<ggrid, 256>>>(query, wq, qb, 1);
    qass_mma<<<NB*NH*NTOK/128, 256>>>(wg1, wg2, wb1, wb2, nctx);

    cudaEventRecord(e1, s1);
    cudaEventRecord(e2, s2);
    cudaStreamWaitEvent(0, e1, 0);
    cudaStreamWaitEvent(0, e2, 0);

    flash_bf16x3<<<dim3(NTOK/128, NB*NH), 256, FLASH_SMEM>>>(ab);

    gemm_bf16x3<<<ggrid, 256>>>(ab, wo, (float*)d_out, 0);
}